// round 4
// baseline (speedup 1.0000x reference)
#include <cuda_runtime.h>

#define FULLM 0xffffffffu
typedef unsigned long long ull;

static __device__ __forceinline__ ull fma2(ull a, ull b, ull c){
    ull d; asm("fma.rn.f32x2 %0, %1, %2, %3;" : "=l"(d) : "l"(a), "l"(b), "l"(c)); return d;
}
static __device__ __forceinline__ ull mul2(ull a, ull b){
    ull d; asm("mul.rn.f32x2 %0, %1, %2;" : "=l"(d) : "l"(a), "l"(b)); return d;
}
static __device__ __forceinline__ ull dup2(float x){
    ull d; asm("mov.b64 %0, {%1, %1};" : "=l"(d) : "f"(x)); return d;
}
static __device__ __forceinline__ ull pack2(float a, float b){
    ull d; asm("mov.b64 %0, {%1, %2};" : "=l"(d) : "f"(a), "f"(b)); return d;
}
static __device__ __forceinline__ float2 unpk(ull a){
    float2 f; asm("mov.b64 {%0, %1}, %2;" : "=f"(f.x), "=f"(f.y) : "l"(a)); return f;
}

// packed softplus: one MUFU (ex2) per element; ln(1+e) via degree-12 poly on fma2 pipe.
// e = 2^(-|x|*log2e) in [0,1]; z = (e-0.5)*(2/3) in [-1/3,1/3];
// ln(1+e) = ln(1.5) + sum_{k=1..12} (-1)^(k+1) z^k / k   (|trunc err| <= (1/3)^13/13 ~ 4.8e-8)
static __device__ __forceinline__ float2 softplus2(ull x){
    ull ax; asm("and.b64 %0, %1, 0x7FFFFFFF7FFFFFFF;" : "=l"(ax) : "l"(x));
    ull t = mul2(ax, dup2(-1.4426950408889634f));
    float2 tf = unpk(t);
    float e0, e1;
    asm("ex2.approx.f32 %0, %1;" : "=f"(e0) : "f"(tf.x));
    asm("ex2.approx.f32 %0, %1;" : "=f"(e1) : "f"(tf.y));
    ull e2 = pack2(e0, e1);
    ull z  = fma2(e2, dup2(0.6666666666666667f), dup2(-0.3333333333333333f));
    ull Q  = dup2(-0.08333333333333333f);                 // -1/12
    Q = fma2(Q, z, dup2( 0.09090909090909091f));          //  1/11
    Q = fma2(Q, z, dup2(-0.1f));
    Q = fma2(Q, z, dup2( 0.1111111111111111f));
    Q = fma2(Q, z, dup2(-0.125f));
    Q = fma2(Q, z, dup2( 0.14285714285714285f));
    Q = fma2(Q, z, dup2(-0.16666666666666666f));
    Q = fma2(Q, z, dup2( 0.2f));
    Q = fma2(Q, z, dup2(-0.25f));
    Q = fma2(Q, z, dup2( 0.3333333333333333f));
    Q = fma2(Q, z, dup2(-0.5f));
    Q = fma2(Q, z, dup2( 1.0f));
    ull L = fma2(Q, z, dup2(0.4054651081081644f));        // + ln(1.5)
    float2 xf = unpk(x), Lf = unpk(L);
    return make_float2(fmaxf(xf.x, 0.f) + Lf.x, fmaxf(xf.y, 0.f) + Lf.y);
}

constexpr int   BN     = 262144;
constexpr int   GROUPS = BN / 32;
constexpr int   HPAD   = 276;
constexpr float EPSF   = 1e-12f;

__global__ __launch_bounds__(128, 4)
void hist2d_kernel(const float* __restrict__ wi, const float* __restrict__ cond,
                   const float* __restrict__ w0, const float* __restrict__ b0,
                   const float* __restrict__ w1, const float* __restrict__ b1,
                   const float* __restrict__ w2, const float* __restrict__ b2,
                   const float* __restrict__ w3, const float* __restrict__ b3,
                   float* __restrict__ out)
{
    __shared__ __align__(16) float2 s_pair[4][4][32];
    __shared__ __align__(16) float2 s_h[16][32];
    __shared__ float s_rows[32][17];
    __shared__ __align__(16) float s_hist[32][HPAD];

    const int tid  = threadIdx.x;
    const int lane = tid & 31;
    const int w    = tid >> 5;

    const int colHalf  = w & 1;
    const int pairHalf = (w >> 1) * 8;
    const int c0       = colHalf * 128 + lane * 4;
    const int rowg     = colHalf * 8 + (lane >> 2);
    const float4 b3q   = __ldg((const float4*)(b3 + c0));
    const float* w3c   = w3 + c0;

    for (int g = blockIdx.x; g < GROUPS; g += gridDim.x) {
        const int Sblk = g * 32;

        // ================= Phase A: layers 0-2 for this warp's 8 samples =================
        const int S0 = Sblk + w * 8;
        #pragma unroll
        for (int p2 = 0; p2 < 2; ++p2) {
            if (lane < 20) {
                int pl = p2 * 2 + (lane >= 10);
                int i  = lane % 10;
                int sb = S0 + pl * 2;
                s_pair[w][pl][i] = make_float2(__ldg(&cond[sb*10 + i]), __ldg(&cond[sb*10 + 10 + i]));
            }
        }
        __syncwarp();

        ull acc[4];

        // ---- layer 0: 10 -> 32 ----
        {
            ull b = dup2(__ldg(&b0[lane]));
            #pragma unroll
            for (int p = 0; p < 4; ++p) acc[p] = b;
            #pragma unroll
            for (int k = 0; k < 10; k += 2) {
                ull wkA = dup2(__ldg(&w0[k*32 + lane]));
                ull wkB = dup2(__ldg(&w0[(k+1)*32 + lane]));
                #pragma unroll
                for (int p = 0; p < 4; ++p) {
                    ulonglong2 h2 = *(const ulonglong2*)&s_pair[w][p][k];
                    acc[p] = fma2(h2.x, wkA, acc[p]);
                    acc[p] = fma2(h2.y, wkB, acc[p]);
                }
            }
            __syncwarp();
            #pragma unroll
            for (int p = 0; p < 4; ++p) {
                float2 f = unpk(acc[p]);
                s_pair[w][p][lane] = make_float2(fmaxf(f.x, 0.f), fmaxf(f.y, 0.f));
            }
            __syncwarp();
        }

        // ---- layer 1: 32 -> 32 ----
        {
            ull b = dup2(__ldg(&b1[lane]));
            #pragma unroll
            for (int p = 0; p < 4; ++p) acc[p] = b;
            #pragma unroll 8
            for (int k = 0; k < 32; k += 2) {
                ull wkA = dup2(__ldg(&w1[k*32 + lane]));
                ull wkB = dup2(__ldg(&w1[(k+1)*32 + lane]));
                #pragma unroll
                for (int p = 0; p < 4; ++p) {
                    ulonglong2 h2 = *(const ulonglong2*)&s_pair[w][p][k];
                    acc[p] = fma2(h2.x, wkA, acc[p]);
                    acc[p] = fma2(h2.y, wkB, acc[p]);
                }
            }
            __syncwarp();
            #pragma unroll
            for (int p = 0; p < 4; ++p) {
                float2 f = unpk(acc[p]);
                s_pair[w][p][lane] = make_float2(fmaxf(f.x, 0.f), fmaxf(f.y, 0.f));
            }
            __syncwarp();
        }

        // ---- layer 2: 32 -> 32, publish to block-shared s_h ----
        {
            ull b = dup2(__ldg(&b2[lane]));
            #pragma unroll
            for (int p = 0; p < 4; ++p) acc[p] = b;
            #pragma unroll 8
            for (int k = 0; k < 32; k += 2) {
                ull wkA = dup2(__ldg(&w2[k*32 + lane]));
                ull wkB = dup2(__ldg(&w2[(k+1)*32 + lane]));
                #pragma unroll
                for (int p = 0; p < 4; ++p) {
                    ulonglong2 h2 = *(const ulonglong2*)&s_pair[w][p][k];
                    acc[p] = fma2(h2.x, wkA, acc[p]);
                    acc[p] = fma2(h2.y, wkB, acc[p]);
                }
            }
            __syncwarp();
            #pragma unroll
            for (int p = 0; p < 4; ++p) {
                float2 f = unpk(acc[p]);
                s_h[w*4 + p][lane] = make_float2(fmaxf(f.x, 0.f), fmaxf(f.y, 0.f));
            }
        }
        __syncthreads();

        // ====== Phase B: layer 3, 8 pairs x 4 cols/lane (128 cols/warp) ======
        ull acc3[8][4];
        {
            ull d0 = dup2(b3q.x), d1 = dup2(b3q.y), d2 = dup2(b3q.z), d3 = dup2(b3q.w);
            #pragma unroll
            for (int p = 0; p < 8; ++p) {
                acc3[p][0] = d0; acc3[p][1] = d1; acc3[p][2] = d2; acc3[p][3] = d3;
            }
        }
        #pragma unroll 2
        for (int k = 0; k < 32; k += 2) {
            float4 wA = __ldg((const float4*)(w3c + k*256));
            float4 wB = __ldg((const float4*)(w3c + (k+1)*256));
            ull a0 = dup2(wA.x), a1 = dup2(wA.y), a2 = dup2(wA.z), a3 = dup2(wA.w);
            ull e0 = dup2(wB.x), e1 = dup2(wB.y), e2 = dup2(wB.z), e3 = dup2(wB.w);
            #pragma unroll
            for (int p = 0; p < 8; ++p) {
                ulonglong2 h2 = *(const ulonglong2*)&s_h[pairHalf + p][k];
                acc3[p][0] = fma2(h2.x, a0, acc3[p][0]);
                acc3[p][1] = fma2(h2.x, a1, acc3[p][1]);
                acc3[p][2] = fma2(h2.x, a2, acc3[p][2]);
                acc3[p][3] = fma2(h2.x, a3, acc3[p][3]);
                acc3[p][0] = fma2(h2.y, e0, acc3[p][0]);
                acc3[p][1] = fma2(h2.y, e1, acc3[p][1]);
                acc3[p][2] = fma2(h2.y, e2, acc3[p][2]);
                acc3[p][3] = fma2(h2.y, e3, acc3[p][3]);
            }
        }

        // softplus (packed, 1 MUFU/elem), hist write, row-sum reduction
        #pragma unroll
        for (int p = 0; p < 8; ++p) {
            const int P = pairHalf + p;
            float2 s0 = softplus2(acc3[p][0]);
            float2 s1 = softplus2(acc3[p][1]);
            float2 s2 = softplus2(acc3[p][2]);
            float2 s3 = softplus2(acc3[p][3]);
            *(float4*)&s_hist[2*P    ][c0] = make_float4(s0.x, s1.x, s2.x, s3.x);
            *(float4*)&s_hist[2*P + 1][c0] = make_float4(s0.y, s1.y, s2.y, s3.y);
            float rx = (s0.x + s1.x) + (s2.x + s3.x);
            float ry = (s0.y + s1.y) + (s2.y + s3.y);
            rx += __shfl_xor_sync(FULLM, rx, 1);
            ry += __shfl_xor_sync(FULLM, ry, 1);
            rx += __shfl_xor_sync(FULLM, rx, 2);
            ry += __shfl_xor_sync(FULLM, ry, 2);
            if ((lane & 3) == 0) {
                s_rows[2*P    ][rowg] = rx;
                s_rows[2*P + 1][rowg] = ry;
            }
        }
        __syncthreads();

        // ====== Phase C: inverse-CDF sampling (unnormalized compares), 2 samples/warp ======
        const int li = lane & 15;
        #pragma unroll
        for (int j = 0; j < 4; ++j) {
            const int sa   = w * 8 + 2 * j;
            const int samp = (lane < 16) ? sa : (sa + 1);
            const int S    = Sblk + samp;

            float rowsum = s_rows[samp][li];
            float tot = rowsum;
            #pragma unroll
            for (int o = 1; o < 16; o <<= 1) tot += __shfl_xor_sync(FULLM, tot, o);

            float cdf = rowsum;
            #pragma unroll
            for (int d = 1; d < 16; d <<= 1) {
                float t = __shfl_up_sync(FULLM, cdf, d, 16);
                if (li >= d) cdf += t;
            }

            float u_x = __ldg(&wi[S*2]);
            float u_y = __ldg(&wi[S*2 + 1]);
            float uy  = u_y * tot;

            unsigned bal = __ballot_sync(FULLM, cdf < uy);
            unsigned mym = (lane < 16) ? (bal & 0xFFFFu) : (bal >> 16);
            int   iy   = min(__popc(mym), 15);
            float cdfp = __shfl_sync(FULLM, cdf, max(iy - 1, 0), 16);
            cdfp = (iy > 0) ? cdfp : 0.f;
            float py   = __shfl_sync(FULLM, rowsum, iy, 16);
            float yv   = ((float)iy + __fdividef(uy - cdfp, fmaxf(py, EPSF))) * 0.0625f;

            float hv   = s_hist[samp][iy*16 + li];
            float cdfx = hv;
            #pragma unroll
            for (int d = 1; d < 16; d <<= 1) {
                float t = __shfl_up_sync(FULLM, cdfx, d, 16);
                if (li >= d) cdfx += t;
            }
            float ux = u_x * py;
            unsigned balx = __ballot_sync(FULLM, cdfx < ux);
            unsigned mymx = (lane < 16) ? (balx & 0xFFFFu) : (balx >> 16);
            int   ix    = min(__popc(mymx), 15);
            float cdfxp = __shfl_sync(FULLM, cdfx, max(ix - 1, 0), 16);
            cdfxp = (ix > 0) ? cdfxp : 0.f;
            float px    = __shfl_sync(FULLM, hv, ix, 16);
            float xv    = ((float)ix + __fdividef(ux - cdfxp, fmaxf(px, EPSF))) * 0.0625f;
            float pout  = __fdividef(px, tot) * 64.f;

            if (li == 0) {
                out[S*2]       = xv * 2.f - 1.f;
                out[S*2 + 1]   = yv * 2.f - 1.f;
                out[2*BN + S]  = pout;
            }
        }
        __syncthreads();
    }
}

extern "C" void kernel_launch(void* const* d_in, const int* in_sizes, int n_in,
                              void* d_out, int out_size) {
    const float* wi   = (const float*)d_in[0];
    const float* cond = (const float*)d_in[1];
    const float* w0   = (const float*)d_in[2];
    const float* b0   = (const float*)d_in[3];
    const float* w1   = (const float*)d_in[4];
    const float* b1   = (const float*)d_in[5];
    const float* w2   = (const float*)d_in[6];
    const float* b2   = (const float*)d_in[7];
    const float* w3   = (const float*)d_in[8];
    const float* b3   = (const float*)d_in[9];
    (void)in_sizes; (void)n_in; (void)out_size;
    hist2d_kernel<<<2048, 128>>>(wi, cond, w0, b0, w1, b1, w2, b2, w3, b3, (float*)d_out);
}

// round 6
// speedup vs baseline: 1.0116x; 1.0116x over previous
#include <cuda_runtime.h>

#define FULLM 0xffffffffu
typedef unsigned long long ull;

static __device__ __forceinline__ ull fma2(ull a, ull b, ull c){
    ull d; asm("fma.rn.f32x2 %0, %1, %2, %3;" : "=l"(d) : "l"(a), "l"(b), "l"(c)); return d;
}
static __device__ __forceinline__ ull mul2(ull a, ull b){
    ull d; asm("mul.rn.f32x2 %0, %1, %2;" : "=l"(d) : "l"(a), "l"(b)); return d;
}
static __device__ __forceinline__ ull dup2(float x){
    ull d; asm("mov.b64 %0, {%1, %1};" : "=l"(d) : "f"(x)); return d;
}
static __device__ __forceinline__ ull pack2(float a, float b){
    ull d; asm("mov.b64 %0, {%1, %2};" : "=l"(d) : "f"(a), "f"(b)); return d;
}
static __device__ __forceinline__ float2 unpk(ull a){
    float2 f; asm("mov.b64 {%0, %1}, %2;" : "=f"(f.x), "=f"(f.y) : "l"(a)); return f;
}

// packed softplus: 1 MUFU/elem; ln(1+e) via degree-9 poly (|err| <= (1/3)^10/10 ~ 1.7e-6)
static __device__ __forceinline__ float2 softplus2(ull x){
    ull ax; asm("and.b64 %0, %1, 0x7FFFFFFF7FFFFFFF;" : "=l"(ax) : "l"(x));
    ull t = mul2(ax, dup2(-1.4426950408889634f));
    float2 tf = unpk(t);
    float e0, e1;
    asm("ex2.approx.f32 %0, %1;" : "=f"(e0) : "f"(tf.x));
    asm("ex2.approx.f32 %0, %1;" : "=f"(e1) : "f"(tf.y));
    ull e2 = pack2(e0, e1);
    ull z  = fma2(e2, dup2(0.6666666666666667f), dup2(-0.3333333333333333f));
    ull Q  = dup2(0.1111111111111111f);                  // 1/9
    Q = fma2(Q, z, dup2(-0.125f));
    Q = fma2(Q, z, dup2( 0.14285714285714285f));
    Q = fma2(Q, z, dup2(-0.16666666666666666f));
    Q = fma2(Q, z, dup2( 0.2f));
    Q = fma2(Q, z, dup2(-0.25f));
    Q = fma2(Q, z, dup2( 0.3333333333333333f));
    Q = fma2(Q, z, dup2(-0.5f));
    Q = fma2(Q, z, dup2( 1.0f));
    ull L = fma2(Q, z, dup2(0.4054651081081644f));       // + ln(1.5)
    float2 xf = unpk(x), Lf = unpk(L);
    return make_float2(fmaxf(xf.x, 0.f) + Lf.x, fmaxf(xf.y, 0.f) + Lf.y);
}

constexpr int   BN     = 262144;
constexpr int   GROUPS = BN / 32;
constexpr int   HPAD   = 276;
constexpr float EPSF   = 1e-12f;

__global__ __launch_bounds__(256, 3)
void hist2d_kernel(const float* __restrict__ wi, const float* __restrict__ cond,
                   const float* __restrict__ w0, const float* __restrict__ b0,
                   const float* __restrict__ w1, const float* __restrict__ b1,
                   const float* __restrict__ w2, const float* __restrict__ b2,
                   const float* __restrict__ w3, const float* __restrict__ b3,
                   float* __restrict__ out)
{
    __shared__ __align__(16) float2 s_pair[8][2][32];   // per-warp layer 0-2 activations
    __shared__ __align__(16) float2 s_h[16][32];        // h after layer 2, [pair][k]
    __shared__ float s_rows[32][17];
    __shared__ __align__(16) float s_hist[32][HPAD];

    const int tid  = threadIdx.x;
    const int lane = tid & 31;
    const int w    = tid >> 5;                 // 0..7

    // phase-B tiling: warp = (pairQuarter, colHalf); lane owns 4 consecutive cols
    const int colHalf = w & 1;
    const int pairQ   = (w >> 1) * 4;          // 4 pairs per warp
    const int c0      = colHalf * 128 + lane * 4;
    const int rowg    = colHalf * 8 + (lane >> 2);
    const float4 b3q  = __ldg((const float4*)(b3 + c0));
    const float* w3c  = w3 + c0;

    for (int g = blockIdx.x; g < GROUPS; g += gridDim.x) {
        const int Sblk = g * 32;

        // ============ Phase A: layers 0-2 for this warp's 4 samples (2 pairs) ============
        const int S0 = Sblk + w * 4;
        if (lane < 20) {
            int pl = lane >= 10;
            int i  = lane % 10;
            int sb = S0 + pl * 2;
            s_pair[w][pl][i] = make_float2(__ldg(&cond[sb*10 + i]), __ldg(&cond[sb*10 + 10 + i]));
        }
        __syncwarp();

        ull acc[2];

        // ---- layer 0: 10 -> 32 ----
        {
            ull b = dup2(__ldg(&b0[lane]));
            acc[0] = b; acc[1] = b;
            #pragma unroll
            for (int k = 0; k < 10; k += 2) {
                ull wkA = dup2(__ldg(&w0[k*32 + lane]));
                ull wkB = dup2(__ldg(&w0[(k+1)*32 + lane]));
                #pragma unroll
                for (int p = 0; p < 2; ++p) {
                    ulonglong2 h2 = *(const ulonglong2*)&s_pair[w][p][k];
                    acc[p] = fma2(h2.x, wkA, acc[p]);
                    acc[p] = fma2(h2.y, wkB, acc[p]);
                }
            }
            __syncwarp();
            #pragma unroll
            for (int p = 0; p < 2; ++p) {
                float2 f = unpk(acc[p]);
                s_pair[w][p][lane] = make_float2(fmaxf(f.x, 0.f), fmaxf(f.y, 0.f));
            }
            __syncwarp();
        }

        // ---- layer 1: 32 -> 32 ----
        {
            ull b = dup2(__ldg(&b1[lane]));
            acc[0] = b; acc[1] = b;
            #pragma unroll 8
            for (int k = 0; k < 32; k += 2) {
                ull wkA = dup2(__ldg(&w1[k*32 + lane]));
                ull wkB = dup2(__ldg(&w1[(k+1)*32 + lane]));
                #pragma unroll
                for (int p = 0; p < 2; ++p) {
                    ulonglong2 h2 = *(const ulonglong2*)&s_pair[w][p][k];
                    acc[p] = fma2(h2.x, wkA, acc[p]);
                    acc[p] = fma2(h2.y, wkB, acc[p]);
                }
            }
            __syncwarp();
            #pragma unroll
            for (int p = 0; p < 2; ++p) {
                float2 f = unpk(acc[p]);
                s_pair[w][p][lane] = make_float2(fmaxf(f.x, 0.f), fmaxf(f.y, 0.f));
            }
            __syncwarp();
        }

        // ---- layer 2: 32 -> 32, publish to block-shared s_h ----
        {
            ull b = dup2(__ldg(&b2[lane]));
            acc[0] = b; acc[1] = b;
            #pragma unroll 8
            for (int k = 0; k < 32; k += 2) {
                ull wkA = dup2(__ldg(&w2[k*32 + lane]));
                ull wkB = dup2(__ldg(&w2[(k+1)*32 + lane]));
                #pragma unroll
                for (int p = 0; p < 2; ++p) {
                    ulonglong2 h2 = *(const ulonglong2*)&s_pair[w][p][k];
                    acc[p] = fma2(h2.x, wkA, acc[p]);
                    acc[p] = fma2(h2.y, wkB, acc[p]);
                }
            }
            __syncwarp();
            #pragma unroll
            for (int p = 0; p < 2; ++p) {
                float2 f = unpk(acc[p]);
                s_h[w*2 + p][lane] = make_float2(fmaxf(f.x, 0.f), fmaxf(f.y, 0.f));
            }
        }
        __syncthreads();

        // ====== Phase B: layer 3, 4 pairs x 4 cols/lane (128 cols/warp) ======
        ull acc3[4][4];
        {
            ull d0 = dup2(b3q.x), d1 = dup2(b3q.y), d2 = dup2(b3q.z), d3 = dup2(b3q.w);
            #pragma unroll
            for (int p = 0; p < 4; ++p) {
                acc3[p][0] = d0; acc3[p][1] = d1; acc3[p][2] = d2; acc3[p][3] = d3;
            }
        }
        #pragma unroll 4
        for (int k = 0; k < 32; k += 2) {
            float4 wA = __ldg((const float4*)(w3c + k*256));
            float4 wB = __ldg((const float4*)(w3c + (k+1)*256));
            ull a0 = dup2(wA.x), a1 = dup2(wA.y), a2 = dup2(wA.z), a3 = dup2(wA.w);
            ull e0 = dup2(wB.x), e1 = dup2(wB.y), e2 = dup2(wB.z), e3 = dup2(wB.w);
            #pragma unroll
            for (int p = 0; p < 4; ++p) {
                ulonglong2 h2 = *(const ulonglong2*)&s_h[pairQ + p][k];
                acc3[p][0] = fma2(h2.x, a0, acc3[p][0]);
                acc3[p][1] = fma2(h2.x, a1, acc3[p][1]);
                acc3[p][2] = fma2(h2.x, a2, acc3[p][2]);
                acc3[p][3] = fma2(h2.x, a3, acc3[p][3]);
                acc3[p][0] = fma2(h2.y, e0, acc3[p][0]);
                acc3[p][1] = fma2(h2.y, e1, acc3[p][1]);
                acc3[p][2] = fma2(h2.y, e2, acc3[p][2]);
                acc3[p][3] = fma2(h2.y, e3, acc3[p][3]);
            }
        }

        // softplus (packed), hist write (STS.128), row-sum reduction (4-lane butterflies)
        #pragma unroll
        for (int p = 0; p < 4; ++p) {
            const int P = pairQ + p;
            float2 s0 = softplus2(acc3[p][0]);
            float2 s1 = softplus2(acc3[p][1]);
            float2 s2 = softplus2(acc3[p][2]);
            float2 s3 = softplus2(acc3[p][3]);
            *(float4*)&s_hist[2*P    ][c0] = make_float4(s0.x, s1.x, s2.x, s3.x);
            *(float4*)&s_hist[2*P + 1][c0] = make_float4(s0.y, s1.y, s2.y, s3.y);
            float rx = (s0.x + s1.x) + (s2.x + s3.x);
            float ry = (s0.y + s1.y) + (s2.y + s3.y);
            rx += __shfl_xor_sync(FULLM, rx, 1);
            ry += __shfl_xor_sync(FULLM, ry, 1);
            rx += __shfl_xor_sync(FULLM, rx, 2);
            ry += __shfl_xor_sync(FULLM, ry, 2);
            if ((lane & 3) == 0) {
                s_rows[2*P    ][rowg] = rx;
                s_rows[2*P + 1][rowg] = ry;
            }
        }
        __syncthreads();

        // ====== Phase C: inverse-CDF sampling (unnormalized compares), 2 samples/warp/iter ======
        const int li = lane & 15;
        #pragma unroll
        for (int j = 0; j < 2; ++j) {
            const int sa   = w * 4 + 2 * j;
            const int samp = (lane < 16) ? sa : (sa + 1);
            const int S    = Sblk + samp;

            float rowsum = s_rows[samp][li];
            float tot = rowsum;
            #pragma unroll
            for (int o = 1; o < 16; o <<= 1) tot += __shfl_xor_sync(FULLM, tot, o);

            float cdf = rowsum;
            #pragma unroll
            for (int d = 1; d < 16; d <<= 1) {
                float t = __shfl_up_sync(FULLM, cdf, d, 16);
                if (li >= d) cdf += t;
            }

            float u_x = __ldg(&wi[S*2]);
            float u_y = __ldg(&wi[S*2 + 1]);
            float uy  = u_y * tot;

            unsigned bal = __ballot_sync(FULLM, cdf < uy);
            unsigned mym = (lane < 16) ? (bal & 0xFFFFu) : (bal >> 16);
            int   iy   = min(__popc(mym), 15);
            float cdfp = __shfl_sync(FULLM, cdf, max(iy - 1, 0), 16);
            cdfp = (iy > 0) ? cdfp : 0.f;
            float py   = __shfl_sync(FULLM, rowsum, iy, 16);
            float yv   = ((float)iy + __fdividef(uy - cdfp, fmaxf(py, EPSF))) * 0.0625f;

            float hv   = s_hist[samp][iy*16 + li];
            float cdfx = hv;
            #pragma unroll
            for (int d = 1; d < 16; d <<= 1) {
                float t = __shfl_up_sync(FULLM, cdfx, d, 16);
                if (li >= d) cdfx += t;
            }
            float ux = u_x * py;
            unsigned balx = __ballot_sync(FULLM, cdfx < ux);
            unsigned mymx = (lane < 16) ? (balx & 0xFFFFu) : (balx >> 16);
            int   ix    = min(__popc(mymx), 15);
            float cdfxp = __shfl_sync(FULLM, cdfx, max(ix - 1, 0), 16);
            cdfxp = (ix > 0) ? cdfxp : 0.f;
            float px    = __shfl_sync(FULLM, hv, ix, 16);
            float xv    = ((float)ix + __fdividef(ux - cdfxp, fmaxf(px, EPSF))) * 0.0625f;
            float pout  = __fdividef(px, tot) * 64.f;

            if (li == 0) {
                out[S*2]       = xv * 2.f - 1.f;
                out[S*2 + 1]   = yv * 2.f - 1.f;
                out[2*BN + S]  = pout;
            }
        }
        __syncthreads();
    }
}

extern "C" void kernel_launch(void* const* d_in, const int* in_sizes, int n_in,
                              void* d_out, int out_size) {
    const float* wi   = (const float*)d_in[0];
    const float* cond = (const float*)d_in[1];
    const float* w0   = (const float*)d_in[2];
    const float* b0   = (const float*)d_in[3];
    const float* w1   = (const float*)d_in[4];
    const float* b1   = (const float*)d_in[5];
    const float* w2   = (const float*)d_in[6];
    const float* b2   = (const float*)d_in[7];
    const float* w3   = (const float*)d_in[8];
    const float* b3   = (const float*)d_in[9];
    (void)in_sizes; (void)n_in; (void)out_size;
    hist2d_kernel<<<2048, 256>>>(wi, cond, w0, b0, w1, b1, w2, b2, w3, b3, (float*)d_out);
}

// round 7
// speedup vs baseline: 1.0308x; 1.0190x over previous
#include <cuda_runtime.h>
#include <cstdint>

#define FULLM 0xffffffffu
typedef unsigned long long ull;
typedef unsigned int uint;

static __device__ __forceinline__ ull fma2(ull a, ull b, ull c){
    ull d; asm("fma.rn.f32x2 %0, %1, %2, %3;" : "=l"(d) : "l"(a), "l"(b), "l"(c)); return d;
}
static __device__ __forceinline__ ull mul2(ull a, ull b){
    ull d; asm("mul.rn.f32x2 %0, %1, %2;" : "=l"(d) : "l"(a), "l"(b)); return d;
}
static __device__ __forceinline__ ull dup2(float x){
    ull d; asm("mov.b64 %0, {%1, %1};" : "=l"(d) : "f"(x)); return d;
}
static __device__ __forceinline__ ull pack2(float a, float b){
    ull d; asm("mov.b64 %0, {%1, %2};" : "=l"(d) : "f"(a), "f"(b)); return d;
}
static __device__ __forceinline__ float2 unpk(ull a){
    float2 f; asm("mov.b64 {%0, %1}, %2;" : "=f"(f.x), "=f"(f.y) : "l"(a)); return f;
}
static __device__ __forceinline__ uint to_tf32(float x){
    uint r; asm("cvt.rna.tf32.f32 %0, %1;" : "=r"(r) : "f"(x)); return r;
}
static __device__ __forceinline__ void mma_tf32(float c[4], const uint a[4], uint b0, uint b1){
    asm("mma.sync.aligned.m16n8k8.row.col.f32.tf32.tf32.f32 "
        "{%0,%1,%2,%3}, {%4,%5,%6,%7}, {%8,%9}, {%0,%1,%2,%3};"
        : "+f"(c[0]), "+f"(c[1]), "+f"(c[2]), "+f"(c[3])
        : "r"(a[0]), "r"(a[1]), "r"(a[2]), "r"(a[3]), "r"(b0), "r"(b1));
}

// packed softplus: 1 MUFU/elem; ln(1+e) via degree-9 poly (|err| <= 1.7e-6)
static __device__ __forceinline__ float2 softplus2(ull x){
    ull ax; asm("and.b64 %0, %1, 0x7FFFFFFF7FFFFFFF;" : "=l"(ax) : "l"(x));
    ull t = mul2(ax, dup2(-1.4426950408889634f));
    float2 tf = unpk(t);
    float e0, e1;
    asm("ex2.approx.f32 %0, %1;" : "=f"(e0) : "f"(tf.x));
    asm("ex2.approx.f32 %0, %1;" : "=f"(e1) : "f"(tf.y));
    ull e2 = pack2(e0, e1);
    ull z  = fma2(e2, dup2(0.6666666666666667f), dup2(-0.3333333333333333f));
    ull Q  = dup2(0.1111111111111111f);
    Q = fma2(Q, z, dup2(-0.125f));
    Q = fma2(Q, z, dup2( 0.14285714285714285f));
    Q = fma2(Q, z, dup2(-0.16666666666666666f));
    Q = fma2(Q, z, dup2( 0.2f));
    Q = fma2(Q, z, dup2(-0.25f));
    Q = fma2(Q, z, dup2( 0.3333333333333333f));
    Q = fma2(Q, z, dup2(-0.5f));
    Q = fma2(Q, z, dup2( 1.0f));
    ull L = fma2(Q, z, dup2(0.4054651081081644f));
    float2 xf = unpk(x), Lf = unpk(L);
    return make_float2(fmaxf(xf.x, 0.f) + Lf.x, fmaxf(xf.y, 0.f) + Lf.y);
}

constexpr int   BN     = 262144;
constexpr int   GROUPS = BN / 32;
constexpr int   HPAD   = 276;
constexpr int   HAS    = 36;        // s_hA row stride: banks (4r+k)%32 all-distinct
constexpr float EPSF   = 1e-12f;

__global__ __launch_bounds__(256, 2)
void hist2d_kernel(const float* __restrict__ wi, const float* __restrict__ cond,
                   const float* __restrict__ w0, const float* __restrict__ b0,
                   const float* __restrict__ w1, const float* __restrict__ b1,
                   const float* __restrict__ w2, const float* __restrict__ b2,
                   const float* __restrict__ w3, const float* __restrict__ b3,
                   float* __restrict__ out)
{
    __shared__ __align__(16) float2 s_pair[8][2][32];   // phase-A activations
    __shared__ __align__(8)  float  s_hA[32 * HAS];     // h after layer 2, [sample][k], pad 36
    __shared__ float s_rows[32][17];
    __shared__ __align__(16) float s_hist[32][HPAD];

    const int tid  = threadIdx.x;
    const int lane = tid & 31;
    const int w    = tid >> 5;          // warp 0..7
    const int gid  = lane >> 2;         // mma groupID
    const int tig  = lane & 3;          // mma threadID_in_group
    const int n0   = w * 32;            // this warp's 32-column slice of layer-3 output

    // ---- persistent B fragments (w3) with 3xTF32 split + bias pairs ----
    uint bhi[4][4][2], blo[4][4][2];
    float2 biasj[4];
    #pragma unroll
    for (int ik = 0; ik < 4; ++ik) {
        #pragma unroll
        for (int j = 0; j < 4; ++j) {
            float v0 = __ldg(&w3[(ik*8 + tig    )*256 + n0 + j*8 + gid]);
            float v1 = __ldg(&w3[(ik*8 + tig + 4)*256 + n0 + j*8 + gid]);
            uint h0 = to_tf32(v0);
            uint h1 = to_tf32(v1);
            bhi[ik][j][0] = h0;  blo[ik][j][0] = to_tf32(v0 - __uint_as_float(h0));
            bhi[ik][j][1] = h1;  blo[ik][j][1] = to_tf32(v1 - __uint_as_float(h1));
        }
    }
    #pragma unroll
    for (int j = 0; j < 4; ++j) {
        biasj[j].x = __ldg(&b3[n0 + j*8 + 2*tig]);
        biasj[j].y = __ldg(&b3[n0 + j*8 + 2*tig + 1]);
    }

    for (int g = blockIdx.x; g < GROUPS; g += gridDim.x) {
        const int Sblk = g * 32;

        // ============ Phase A: layers 0-2, warp handles samples 4w..4w+3 (2 pairs) ============
        const int S0 = Sblk + w * 4;
        if (lane < 20) {
            int pl = lane >= 10;
            int i  = lane % 10;
            int sb = S0 + pl * 2;
            s_pair[w][pl][i] = make_float2(__ldg(&cond[sb*10 + i]), __ldg(&cond[sb*10 + 10 + i]));
        }
        __syncwarp();

        ull acc[2];

        // layer 0: 10 -> 32
        {
            ull b = dup2(__ldg(&b0[lane]));
            acc[0] = b; acc[1] = b;
            #pragma unroll
            for (int k = 0; k < 10; k += 2) {
                ull wkA = dup2(__ldg(&w0[k*32 + lane]));
                ull wkB = dup2(__ldg(&w0[(k+1)*32 + lane]));
                #pragma unroll
                for (int p = 0; p < 2; ++p) {
                    ulonglong2 h2 = *(const ulonglong2*)&s_pair[w][p][k];
                    acc[p] = fma2(h2.x, wkA, acc[p]);
                    acc[p] = fma2(h2.y, wkB, acc[p]);
                }
            }
            __syncwarp();
            #pragma unroll
            for (int p = 0; p < 2; ++p) {
                float2 f = unpk(acc[p]);
                s_pair[w][p][lane] = make_float2(fmaxf(f.x, 0.f), fmaxf(f.y, 0.f));
            }
            __syncwarp();
        }

        // layer 1: 32 -> 32
        {
            ull b = dup2(__ldg(&b1[lane]));
            acc[0] = b; acc[1] = b;
            #pragma unroll 8
            for (int k = 0; k < 32; k += 2) {
                ull wkA = dup2(__ldg(&w1[k*32 + lane]));
                ull wkB = dup2(__ldg(&w1[(k+1)*32 + lane]));
                #pragma unroll
                for (int p = 0; p < 2; ++p) {
                    ulonglong2 h2 = *(const ulonglong2*)&s_pair[w][p][k];
                    acc[p] = fma2(h2.x, wkA, acc[p]);
                    acc[p] = fma2(h2.y, wkB, acc[p]);
                }
            }
            __syncwarp();
            #pragma unroll
            for (int p = 0; p < 2; ++p) {
                float2 f = unpk(acc[p]);
                s_pair[w][p][lane] = make_float2(fmaxf(f.x, 0.f), fmaxf(f.y, 0.f));
            }
            __syncwarp();
        }

        // layer 2: 32 -> 32, publish to s_hA in plain [sample][k] layout
        {
            ull b = dup2(__ldg(&b2[lane]));
            acc[0] = b; acc[1] = b;
            #pragma unroll 8
            for (int k = 0; k < 32; k += 2) {
                ull wkA = dup2(__ldg(&w2[k*32 + lane]));
                ull wkB = dup2(__ldg(&w2[(k+1)*32 + lane]));
                #pragma unroll
                for (int p = 0; p < 2; ++p) {
                    ulonglong2 h2 = *(const ulonglong2*)&s_pair[w][p][k];
                    acc[p] = fma2(h2.x, wkA, acc[p]);
                    acc[p] = fma2(h2.y, wkB, acc[p]);
                }
            }
            __syncwarp();
            #pragma unroll
            for (int p = 0; p < 2; ++p) {
                float2 f = unpk(acc[p]);
                s_hA[(w*4 + 2*p    ) * HAS + lane] = fmaxf(f.x, 0.f);
                s_hA[(w*4 + 2*p + 1) * HAS + lane] = fmaxf(f.y, 0.f);
            }
        }
        __syncthreads();

        // ============ Phase B: layer 3 via mma m16n8k8 tf32 (3xTF32) ============
        #pragma unroll
        for (int im = 0; im < 2; ++im) {
            float c[4][4];
            #pragma unroll
            for (int j = 0; j < 4; ++j) {
                c[j][0] = biasj[j].x; c[j][1] = biasj[j].y;
                c[j][2] = biasj[j].x; c[j][3] = biasj[j].y;
            }

            const int r0 = im * 16 + gid;
            #pragma unroll
            for (int ik = 0; ik < 4; ++ik) {
                const int k0 = ik * 8;
                float a0 = s_hA[ r0      * HAS + k0 + tig    ];
                float a1 = s_hA[(r0 + 8) * HAS + k0 + tig    ];
                float a2 = s_hA[ r0      * HAS + k0 + tig + 4];
                float a3 = s_hA[(r0 + 8) * HAS + k0 + tig + 4];
                uint ah[4], al[4];
                ah[0] = to_tf32(a0); al[0] = to_tf32(a0 - __uint_as_float(ah[0]));
                ah[1] = to_tf32(a1); al[1] = to_tf32(a1 - __uint_as_float(ah[1]));
                ah[2] = to_tf32(a2); al[2] = to_tf32(a2 - __uint_as_float(ah[2]));
                ah[3] = to_tf32(a3); al[3] = to_tf32(a3 - __uint_as_float(ah[3]));
                #pragma unroll
                for (int j = 0; j < 4; ++j) {
                    mma_tf32(c[j], ah, bhi[ik][j][0], bhi[ik][j][1]);
                    mma_tf32(c[j], ah, blo[ik][j][0], blo[ik][j][1]);
                    mma_tf32(c[j], al, bhi[ik][j][0], bhi[ik][j][1]);
                }
            }

            // epilogue: softplus, hist writes, row sums
            const int m0 = im * 16 + gid;      // sample (rows m0 and m0+8)
            float rs_lo0 = 0.f, rs_hi0 = 0.f, rs_lo8 = 0.f, rs_hi8 = 0.f;
            #pragma unroll
            for (int j = 0; j < 4; ++j) {
                float2 s01 = softplus2(pack2(c[j][0], c[j][1]));   // sample m0,  cols colb..+1
                float2 s23 = softplus2(pack2(c[j][2], c[j][3]));   // sample m0+8
                const int colb = n0 + j*8 + 2*tig;
                *(float2*)&s_hist[m0    ][colb] = s01;
                *(float2*)&s_hist[m0 + 8][colb] = s23;
                float t0 = s01.x + s01.y;
                float t8 = s23.x + s23.y;
                if (j < 2) { rs_lo0 += t0; rs_lo8 += t8; }
                else       { rs_hi0 += t0; rs_hi8 += t8; }
            }
            rs_lo0 += __shfl_xor_sync(FULLM, rs_lo0, 1);
            rs_hi0 += __shfl_xor_sync(FULLM, rs_hi0, 1);
            rs_lo8 += __shfl_xor_sync(FULLM, rs_lo8, 1);
            rs_hi8 += __shfl_xor_sync(FULLM, rs_hi8, 1);
            rs_lo0 += __shfl_xor_sync(FULLM, rs_lo0, 2);
            rs_hi0 += __shfl_xor_sync(FULLM, rs_hi0, 2);
            rs_lo8 += __shfl_xor_sync(FULLM, rs_lo8, 2);
            rs_hi8 += __shfl_xor_sync(FULLM, rs_hi8, 2);
            if (tig == 0) {
                s_rows[m0    ][2*w    ] = rs_lo0;
                s_rows[m0    ][2*w + 1] = rs_hi0;
                s_rows[m0 + 8][2*w    ] = rs_lo8;
                s_rows[m0 + 8][2*w + 1] = rs_hi8;
            }
        }
        __syncthreads();

        // ============ Phase C: inverse-CDF sampling (unnormalized compares) ============
        const int li = lane & 15;
        #pragma unroll
        for (int j = 0; j < 2; ++j) {
            const int sa   = w * 4 + 2 * j;
            const int samp = (lane < 16) ? sa : (sa + 1);
            const int S    = Sblk + samp;

            float rowsum = s_rows[samp][li];
            float tot = rowsum;
            #pragma unroll
            for (int o = 1; o < 16; o <<= 1) tot += __shfl_xor_sync(FULLM, tot, o);

            float cdf = rowsum;
            #pragma unroll
            for (int d = 1; d < 16; d <<= 1) {
                float t = __shfl_up_sync(FULLM, cdf, d, 16);
                if (li >= d) cdf += t;
            }

            float u_x = __ldg(&wi[S*2]);
            float u_y = __ldg(&wi[S*2 + 1]);
            float uy  = u_y * tot;

            unsigned bal = __ballot_sync(FULLM, cdf < uy);
            unsigned mym = (lane < 16) ? (bal & 0xFFFFu) : (bal >> 16);
            int   iy   = min(__popc(mym), 15);
            float cdfp = __shfl_sync(FULLM, cdf, max(iy - 1, 0), 16);
            cdfp = (iy > 0) ? cdfp : 0.f;
            float py   = __shfl_sync(FULLM, rowsum, iy, 16);
            float yv   = ((float)iy + __fdividef(uy - cdfp, fmaxf(py, EPSF))) * 0.0625f;

            float hv   = s_hist[samp][iy*16 + li];
            float cdfx = hv;
            #pragma unroll
            for (int d = 1; d < 16; d <<= 1) {
                float t = __shfl_up_sync(FULLM, cdfx, d, 16);
                if (li >= d) cdfx += t;
            }
            float ux = u_x * py;
            unsigned balx = __ballot_sync(FULLM, cdfx < ux);
            unsigned mymx = (lane < 16) ? (balx & 0xFFFFu) : (balx >> 16);
            int   ix    = min(__popc(mymx), 15);
            float cdfxp = __shfl_sync(FULLM, cdfx, max(ix - 1, 0), 16);
            cdfxp = (ix > 0) ? cdfxp : 0.f;
            float px    = __shfl_sync(FULLM, hv, ix, 16);
            float xv    = ((float)ix + __fdividef(ux - cdfxp, fmaxf(px, EPSF))) * 0.0625f;
            float pout  = __fdividef(px, tot) * 64.f;

            if (li == 0) {
                out[S*2]       = xv * 2.f - 1.f;
                out[S*2 + 1]   = yv * 2.f - 1.f;
                out[2*BN + S]  = pout;
            }
        }
        __syncthreads();
    }
}

extern "C" void kernel_launch(void* const* d_in, const int* in_sizes, int n_in,
                              void* d_out, int out_size) {
    const float* wi   = (const float*)d_in[0];
    const float* cond = (const float*)d_in[1];
    const float* w0   = (const float*)d_in[2];
    const float* b0   = (const float*)d_in[3];
    const float* w1   = (const float*)d_in[4];
    const float* b1   = (const float*)d_in[5];
    const float* w2   = (const float*)d_in[6];
    const float* b2   = (const float*)d_in[7];
    const float* w3   = (const float*)d_in[8];
    const float* b3   = (const float*)d_in[9];
    (void)in_sizes; (void)n_in; (void)out_size;
    hist2d_kernel<<<2048, 256>>>(wi, cond, w0, b0, w1, b1, w2, b2, w3, b3, (float*)d_out);
}

// round 8
// speedup vs baseline: 1.0419x; 1.0108x over previous
#include <cuda_runtime.h>
#include <cstdint>

#define FULLM 0xffffffffu
typedef unsigned long long ull;
typedef unsigned int uint;

static __device__ __forceinline__ ull fma2(ull a, ull b, ull c){
    ull d; asm("fma.rn.f32x2 %0, %1, %2, %3;" : "=l"(d) : "l"(a), "l"(b), "l"(c)); return d;
}
static __device__ __forceinline__ ull mul2(ull a, ull b){
    ull d; asm("mul.rn.f32x2 %0, %1, %2;" : "=l"(d) : "l"(a), "l"(b)); return d;
}
static __device__ __forceinline__ ull dup2(float x){
    ull d; asm("mov.b64 %0, {%1, %1};" : "=l"(d) : "f"(x)); return d;
}
static __device__ __forceinline__ ull pack2(float a, float b){
    ull d; asm("mov.b64 %0, {%1, %2};" : "=l"(d) : "f"(a), "f"(b)); return d;
}
static __device__ __forceinline__ float2 unpk(ull a){
    float2 f; asm("mov.b64 {%0, %1}, %2;" : "=f"(f.x), "=f"(f.y) : "l"(a)); return f;
}
static __device__ __forceinline__ uint to_tf32(float x){
    uint r; asm("cvt.rna.tf32.f32 %0, %1;" : "=r"(r) : "f"(x)); return r;
}
static __device__ __forceinline__ void mma_tf32(float c[4], const uint a[4], uint b0, uint b1){
    asm("mma.sync.aligned.m16n8k8.row.col.f32.tf32.tf32.f32 "
        "{%0,%1,%2,%3}, {%4,%5,%6,%7}, {%8,%9}, {%0,%1,%2,%3};"
        : "+f"(c[0]), "+f"(c[1]), "+f"(c[2]), "+f"(c[3])
        : "r"(a[0]), "r"(a[1]), "r"(a[2]), "r"(a[3]), "r"(b0), "r"(b1));
}

// packed softplus: 1 MUFU/elem; ln(1+e) via degree-9 poly (|err| <= 1.7e-6)
static __device__ __forceinline__ float2 softplus2(ull x){
    ull ax; asm("and.b64 %0, %1, 0x7FFFFFFF7FFFFFFF;" : "=l"(ax) : "l"(x));
    ull t = mul2(ax, dup2(-1.4426950408889634f));
    float2 tf = unpk(t);
    float e0, e1;
    asm("ex2.approx.f32 %0, %1;" : "=f"(e0) : "f"(tf.x));
    asm("ex2.approx.f32 %0, %1;" : "=f"(e1) : "f"(tf.y));
    ull e2 = pack2(e0, e1);
    ull z  = fma2(e2, dup2(0.6666666666666667f), dup2(-0.3333333333333333f));
    ull Q  = dup2(0.1111111111111111f);
    Q = fma2(Q, z, dup2(-0.125f));
    Q = fma2(Q, z, dup2( 0.14285714285714285f));
    Q = fma2(Q, z, dup2(-0.16666666666666666f));
    Q = fma2(Q, z, dup2( 0.2f));
    Q = fma2(Q, z, dup2(-0.25f));
    Q = fma2(Q, z, dup2( 0.3333333333333333f));
    Q = fma2(Q, z, dup2(-0.5f));
    Q = fma2(Q, z, dup2( 1.0f));
    ull L = fma2(Q, z, dup2(0.4054651081081644f));
    float2 xf = unpk(x), Lf = unpk(L);
    return make_float2(fmaxf(xf.x, 0.f) + Lf.x, fmaxf(xf.y, 0.f) + Lf.y);
}

constexpr int   BN     = 262144;
constexpr int   GROUPS = BN / 32;
constexpr int   HPAD   = 276;
constexpr int   HAS    = 36;
constexpr float EPSF   = 1e-12f;

__global__ __launch_bounds__(256, 2)
void hist2d_kernel(const float* __restrict__ wi, const float* __restrict__ cond,
                   const float* __restrict__ w0, const float* __restrict__ b0,
                   const float* __restrict__ w1, const float* __restrict__ b1,
                   const float* __restrict__ w2, const float* __restrict__ b2,
                   const float* __restrict__ w3, const float* __restrict__ b3,
                   float* __restrict__ out)
{
    __shared__ __align__(16) float2 s_pair[8][2][32];
    __shared__ __align__(8)  float  s_hA[32 * HAS];
    __shared__ float s_rows[32][17];
    __shared__ __align__(16) float s_hist[32][HPAD];

    const int tid  = threadIdx.x;
    const int lane = tid & 31;
    const int w    = tid >> 5;
    const int gid  = lane >> 2;
    const int tig  = lane & 3;
    const int n0   = w * 32;

    // persistent B fragments (w3) with 3xTF32 split + bias pairs
    uint bhi[4][4][2], blo[4][4][2];
    float2 biasj[4];
    #pragma unroll
    for (int ik = 0; ik < 4; ++ik) {
        #pragma unroll
        for (int j = 0; j < 4; ++j) {
            float v0 = __ldg(&w3[(ik*8 + tig    )*256 + n0 + j*8 + gid]);
            float v1 = __ldg(&w3[(ik*8 + tig + 4)*256 + n0 + j*8 + gid]);
            uint h0 = to_tf32(v0);
            uint h1 = to_tf32(v1);
            bhi[ik][j][0] = h0;  blo[ik][j][0] = to_tf32(v0 - __uint_as_float(h0));
            bhi[ik][j][1] = h1;  blo[ik][j][1] = to_tf32(v1 - __uint_as_float(h1));
        }
    }
    #pragma unroll
    for (int j = 0; j < 4; ++j) {
        biasj[j].x = __ldg(&b3[n0 + j*8 + 2*tig]);
        biasj[j].y = __ldg(&b3[n0 + j*8 + 2*tig + 1]);
    }

    // ---- Phase A (layers 0-2 for this warp's 4 samples of group gg) ----
    auto phaseA = [&](int gg) {
        const int S0 = gg * 32 + w * 4;
        if (lane < 20) {
            int pl = lane >= 10;
            int i  = lane % 10;
            int sb = S0 + pl * 2;
            s_pair[w][pl][i] = make_float2(__ldg(&cond[sb*10 + i]), __ldg(&cond[sb*10 + 10 + i]));
        }
        __syncwarp();

        ull acc[2];

        // layer 0: 10 -> 32
        {
            ull b = dup2(__ldg(&b0[lane]));
            acc[0] = b; acc[1] = b;
            #pragma unroll
            for (int k = 0; k < 10; k += 2) {
                ull wkA = dup2(__ldg(&w0[k*32 + lane]));
                ull wkB = dup2(__ldg(&w0[(k+1)*32 + lane]));
                #pragma unroll
                for (int p = 0; p < 2; ++p) {
                    ulonglong2 h2 = *(const ulonglong2*)&s_pair[w][p][k];
                    acc[p] = fma2(h2.x, wkA, acc[p]);
                    acc[p] = fma2(h2.y, wkB, acc[p]);
                }
            }
            __syncwarp();
            #pragma unroll
            for (int p = 0; p < 2; ++p) {
                float2 f = unpk(acc[p]);
                s_pair[w][p][lane] = make_float2(fmaxf(f.x, 0.f), fmaxf(f.y, 0.f));
            }
            __syncwarp();
        }

        // layer 1: 32 -> 32
        {
            ull b = dup2(__ldg(&b1[lane]));
            acc[0] = b; acc[1] = b;
            #pragma unroll 8
            for (int k = 0; k < 32; k += 2) {
                ull wkA = dup2(__ldg(&w1[k*32 + lane]));
                ull wkB = dup2(__ldg(&w1[(k+1)*32 + lane]));
                #pragma unroll
                for (int p = 0; p < 2; ++p) {
                    ulonglong2 h2 = *(const ulonglong2*)&s_pair[w][p][k];
                    acc[p] = fma2(h2.x, wkA, acc[p]);
                    acc[p] = fma2(h2.y, wkB, acc[p]);
                }
            }
            __syncwarp();
            #pragma unroll
            for (int p = 0; p < 2; ++p) {
                float2 f = unpk(acc[p]);
                s_pair[w][p][lane] = make_float2(fmaxf(f.x, 0.f), fmaxf(f.y, 0.f));
            }
            __syncwarp();
        }

        // layer 2: 32 -> 32, publish to s_hA [sample][k]
        {
            ull b = dup2(__ldg(&b2[lane]));
            acc[0] = b; acc[1] = b;
            #pragma unroll 8
            for (int k = 0; k < 32; k += 2) {
                ull wkA = dup2(__ldg(&w2[k*32 + lane]));
                ull wkB = dup2(__ldg(&w2[(k+1)*32 + lane]));
                #pragma unroll
                for (int p = 0; p < 2; ++p) {
                    ulonglong2 h2 = *(const ulonglong2*)&s_pair[w][p][k];
                    acc[p] = fma2(h2.x, wkA, acc[p]);
                    acc[p] = fma2(h2.y, wkB, acc[p]);
                }
            }
            __syncwarp();
            #pragma unroll
            for (int p = 0; p < 2; ++p) {
                float2 f = unpk(acc[p]);
                s_hA[(w*4 + 2*p    ) * HAS + lane] = fmaxf(f.x, 0.f);
                s_hA[(w*4 + 2*p + 1) * HAS + lane] = fmaxf(f.y, 0.f);
            }
        }
    };

    int g = blockIdx.x;
    if (g < GROUPS) phaseA(g);     // prologue

    for (; g < GROUPS; g += gridDim.x) {
        const int Sblk = g * 32;
        __syncthreads();   // barrier 1: s_hA(g) ready; prior C done with s_hist/s_rows

        // ============ Phase B: layer 3 via mma m16n8k8 tf32 (3xTF32) ============
        #pragma unroll
        for (int im = 0; im < 2; ++im) {
            float c[4][4];
            #pragma unroll
            for (int j = 0; j < 4; ++j) {
                c[j][0] = biasj[j].x; c[j][1] = biasj[j].y;
                c[j][2] = biasj[j].x; c[j][3] = biasj[j].y;
            }

            const int r0 = im * 16 + gid;
            #pragma unroll
            for (int ik = 0; ik < 4; ++ik) {
                const int k0 = ik * 8;
                float a0 = s_hA[ r0      * HAS + k0 + tig    ];
                float a1 = s_hA[(r0 + 8) * HAS + k0 + tig    ];
                float a2 = s_hA[ r0      * HAS + k0 + tig + 4];
                float a3 = s_hA[(r0 + 8) * HAS + k0 + tig + 4];
                uint ah[4], al[4];
                ah[0] = to_tf32(a0); al[0] = to_tf32(a0 - __uint_as_float(ah[0]));
                ah[1] = to_tf32(a1); al[1] = to_tf32(a1 - __uint_as_float(ah[1]));
                ah[2] = to_tf32(a2); al[2] = to_tf32(a2 - __uint_as_float(ah[2]));
                ah[3] = to_tf32(a3); al[3] = to_tf32(a3 - __uint_as_float(ah[3]));
                #pragma unroll
                for (int j = 0; j < 4; ++j) {
                    mma_tf32(c[j], ah, bhi[ik][j][0], bhi[ik][j][1]);
                    mma_tf32(c[j], ah, blo[ik][j][0], blo[ik][j][1]);
                    mma_tf32(c[j], al, bhi[ik][j][0], bhi[ik][j][1]);
                }
            }

            // epilogue: softplus, hist writes, row sums
            const int m0 = im * 16 + gid;
            float rs_lo0 = 0.f, rs_hi0 = 0.f, rs_lo8 = 0.f, rs_hi8 = 0.f;
            #pragma unroll
            for (int j = 0; j < 4; ++j) {
                float2 s01 = softplus2(pack2(c[j][0], c[j][1]));
                float2 s23 = softplus2(pack2(c[j][2], c[j][3]));
                const int colb = n0 + j*8 + 2*tig;
                *(float2*)&s_hist[m0    ][colb] = s01;
                *(float2*)&s_hist[m0 + 8][colb] = s23;
                float t0 = s01.x + s01.y;
                float t8 = s23.x + s23.y;
                if (j < 2) { rs_lo0 += t0; rs_lo8 += t8; }
                else       { rs_hi0 += t0; rs_hi8 += t8; }
            }
            rs_lo0 += __shfl_xor_sync(FULLM, rs_lo0, 1);
            rs_hi0 += __shfl_xor_sync(FULLM, rs_hi0, 1);
            rs_lo8 += __shfl_xor_sync(FULLM, rs_lo8, 1);
            rs_hi8 += __shfl_xor_sync(FULLM, rs_hi8, 1);
            rs_lo0 += __shfl_xor_sync(FULLM, rs_lo0, 2);
            rs_hi0 += __shfl_xor_sync(FULLM, rs_hi0, 2);
            rs_lo8 += __shfl_xor_sync(FULLM, rs_lo8, 2);
            rs_hi8 += __shfl_xor_sync(FULLM, rs_hi8, 2);
            if (tig == 0) {
                s_rows[m0    ][2*w    ] = rs_lo0;
                s_rows[m0    ][2*w + 1] = rs_hi0;
                s_rows[m0 + 8][2*w    ] = rs_lo8;
                s_rows[m0 + 8][2*w + 1] = rs_hi8;
            }
        }
        __syncthreads();   // barrier 2: s_hist/s_rows ready; s_hA free for next A

        // ---- pipelined: phase A of the NEXT group fills phase-C stall cycles ----
        const int gn = g + gridDim.x;
        if (gn < GROUPS) phaseA(gn);

        // ============ Phase C: inverse-CDF sampling (unnormalized compares) ============
        const int li = lane & 15;
        #pragma unroll
        for (int j = 0; j < 2; ++j) {
            const int sa   = w * 4 + 2 * j;
            const int samp = (lane < 16) ? sa : (sa + 1);
            const int S    = Sblk + samp;

            float rowsum = s_rows[samp][li];
            float tot = rowsum;
            #pragma unroll
            for (int o = 1; o < 16; o <<= 1) tot += __shfl_xor_sync(FULLM, tot, o);

            float cdf = rowsum;
            #pragma unroll
            for (int d = 1; d < 16; d <<= 1) {
                float t = __shfl_up_sync(FULLM, cdf, d, 16);
                if (li >= d) cdf += t;
            }

            float u_x = __ldg(&wi[S*2]);
            float u_y = __ldg(&wi[S*2 + 1]);
            float uy  = u_y * tot;

            unsigned bal = __ballot_sync(FULLM, cdf < uy);
            unsigned mym = (lane < 16) ? (bal & 0xFFFFu) : (bal >> 16);
            int   iy   = min(__popc(mym), 15);
            float cdfp = __shfl_sync(FULLM, cdf, max(iy - 1, 0), 16);
            cdfp = (iy > 0) ? cdfp : 0.f;
            float py   = __shfl_sync(FULLM, rowsum, iy, 16);
            float yv   = ((float)iy + __fdividef(uy - cdfp, fmaxf(py, EPSF))) * 0.0625f;

            float hv   = s_hist[samp][iy*16 + li];
            float cdfx = hv;
            #pragma unroll
            for (int d = 1; d < 16; d <<= 1) {
                float t = __shfl_up_sync(FULLM, cdfx, d, 16);
                if (li >= d) cdfx += t;
            }
            float ux = u_x * py;
            unsigned balx = __ballot_sync(FULLM, cdfx < ux);
            unsigned mymx = (lane < 16) ? (balx & 0xFFFFu) : (balx >> 16);
            int   ix    = min(__popc(mymx), 15);
            float cdfxp = __shfl_sync(FULLM, cdfx, max(ix - 1, 0), 16);
            cdfxp = (ix > 0) ? cdfxp : 0.f;
            float px    = __shfl_sync(FULLM, hv, ix, 16);
            float xv    = ((float)ix + __fdividef(ux - cdfxp, fmaxf(px, EPSF))) * 0.0625f;
            float pout  = __fdividef(px, tot) * 64.f;

            if (li == 0) {
                out[S*2]       = xv * 2.f - 1.f;
                out[S*2 + 1]   = yv * 2.f - 1.f;
                out[2*BN + S]  = pout;
            }
        }
    }
}

extern "C" void kernel_launch(void* const* d_in, const int* in_sizes, int n_in,
                              void* d_out, int out_size) {
    const float* wi   = (const float*)d_in[0];
    const float* cond = (const float*)d_in[1];
    const float* w0   = (const float*)d_in[2];
    const float* b0   = (const float*)d_in[3];
    const float* w1   = (const float*)d_in[4];
    const float* b1   = (const float*)d_in[5];
    const float* w2   = (const float*)d_in[6];
    const float* b2   = (const float*)d_in[7];
    const float* w3   = (const float*)d_in[8];
    const float* b3   = (const float*)d_in[9];
    (void)in_sizes; (void)n_in; (void)out_size;
    hist2d_kernel<<<2048, 256>>>(wi, cond, w0, b0, w1, b1, w2, b2, w3, b3, (float*)d_out);
}

// round 9
// speedup vs baseline: 1.1248x; 1.0796x over previous
#include <cuda_runtime.h>
#include <cstdint>

#define FULLM 0xffffffffu
typedef unsigned long long ull;
typedef unsigned int uint;

static __device__ __forceinline__ ull fma2(ull a, ull b, ull c){
    ull d; asm("fma.rn.f32x2 %0, %1, %2, %3;" : "=l"(d) : "l"(a), "l"(b), "l"(c)); return d;
}
static __device__ __forceinline__ ull add2(ull a, ull b){
    ull d; asm("add.rn.f32x2 %0, %1, %2;" : "=l"(d) : "l"(a), "l"(b)); return d;
}
static __device__ __forceinline__ ull mul2(ull a, ull b){
    ull d; asm("mul.rn.f32x2 %0, %1, %2;" : "=l"(d) : "l"(a), "l"(b)); return d;
}
static __device__ __forceinline__ ull dup2(float x){
    ull d; asm("mov.b64 %0, {%1, %1};" : "=l"(d) : "f"(x)); return d;
}
static __device__ __forceinline__ ull pack2(float a, float b){
    ull d; asm("mov.b64 %0, {%1, %2};" : "=l"(d) : "f"(a), "f"(b)); return d;
}
static __device__ __forceinline__ float2 unpk(ull a){
    float2 f; asm("mov.b64 {%0, %1}, %2;" : "=f"(f.x), "=f"(f.y) : "l"(a)); return f;
}
static __device__ __forceinline__ uint to_tf32(float x){
    uint r; asm("cvt.rna.tf32.f32 %0, %1;" : "=r"(r) : "f"(x)); return r;
}
static __device__ __forceinline__ void mma_tf32(float c[4], const uint a[4], uint b0, uint b1){
    asm("mma.sync.aligned.m16n8k8.row.col.f32.tf32.tf32.f32 "
        "{%0,%1,%2,%3}, {%4,%5,%6,%7}, {%8,%9}, {%0,%1,%2,%3};"
        : "+f"(c[0]), "+f"(c[1]), "+f"(c[2]), "+f"(c[3])
        : "r"(a[0]), "r"(a[1]), "r"(a[2]), "r"(a[3]), "r"(b0), "r"(b1));
}

// packed softplus: 1 MUFU/elem; ln(1+e) via degree-9 poly (|err| <= 1.7e-6)
static __device__ __forceinline__ float2 softplus2(ull x){
    ull ax; asm("and.b64 %0, %1, 0x7FFFFFFF7FFFFFFF;" : "=l"(ax) : "l"(x));
    ull t = mul2(ax, dup2(-1.4426950408889634f));
    float2 tf = unpk(t);
    float e0, e1;
    asm("ex2.approx.f32 %0, %1;" : "=f"(e0) : "f"(tf.x));
    asm("ex2.approx.f32 %0, %1;" : "=f"(e1) : "f"(tf.y));
    ull e2 = pack2(e0, e1);
    ull z  = fma2(e2, dup2(0.6666666666666667f), dup2(-0.3333333333333333f));
    ull Q  = dup2(0.1111111111111111f);
    Q = fma2(Q, z, dup2(-0.125f));
    Q = fma2(Q, z, dup2( 0.14285714285714285f));
    Q = fma2(Q, z, dup2(-0.16666666666666666f));
    Q = fma2(Q, z, dup2( 0.2f));
    Q = fma2(Q, z, dup2(-0.25f));
    Q = fma2(Q, z, dup2( 0.3333333333333333f));
    Q = fma2(Q, z, dup2(-0.5f));
    Q = fma2(Q, z, dup2( 1.0f));
    ull L = fma2(Q, z, dup2(0.4054651081081644f));
    float2 xf = unpk(x), Lf = unpk(L);
    return make_float2(fmaxf(xf.x, 0.f) + Lf.x, fmaxf(xf.y, 0.f) + Lf.y);
}

constexpr int   BN     = 262144;
constexpr int   GROUPS = BN / 32;
constexpr int   HPAD   = 276;
constexpr int   HAS    = 36;
constexpr float EPSF   = 1e-12f;

// w3 fragments packed in mma order: [w][ik][j][lane] -> uint4 {bhi0,bhi1,blo0,blo1}
__device__ uint4 g_w3pack[8 * 4 * 4 * 32];

__global__ void prep_kernel(const float* __restrict__ w3) {
    int idx = blockIdx.x * blockDim.x + threadIdx.x;   // 0..4095
    if (idx >= 4096) return;
    int lane = idx & 31;
    int j    = (idx >> 5) & 3;
    int ik   = (idx >> 7) & 3;
    int w    = idx >> 9;
    int gid  = lane >> 2, tig = lane & 3;
    int n0   = w * 32;
    float v0 = w3[(ik*8 + tig    )*256 + n0 + j*8 + gid];
    float v1 = w3[(ik*8 + tig + 4)*256 + n0 + j*8 + gid];
    uint h0 = to_tf32(v0);
    uint h1 = to_tf32(v1);
    uint l0 = to_tf32(v0 - __uint_as_float(h0));
    uint l1 = to_tf32(v1 - __uint_as_float(h1));
    g_w3pack[idx] = make_uint4(h0, h1, l0, l1);
}

__global__ __launch_bounds__(256, 3)
void hist2d_kernel(const float* __restrict__ wi, const float* __restrict__ cond,
                   const float* __restrict__ w0, const float* __restrict__ b0,
                   const float* __restrict__ w1, const float* __restrict__ b1,
                   const float* __restrict__ w2, const float* __restrict__ b2,
                   const float* __restrict__ b3,
                   float* __restrict__ out)
{
    __shared__ __align__(16) float2 s_pair[8][2][32];
    __shared__ __align__(8)  float  s_hA[32 * HAS];
    __shared__ float s_rows[32][17];
    __shared__ __align__(16) float s_hist[32][HPAD];

    const int tid  = threadIdx.x;
    const int lane = tid & 31;
    const int w    = tid >> 5;
    const int gid  = lane >> 2;
    const int tig  = lane & 3;
    const int n0   = w * 32;

    float2 biasj[4];
    #pragma unroll
    for (int j = 0; j < 4; ++j) {
        biasj[j].x = __ldg(&b3[n0 + j*8 + 2*tig]);
        biasj[j].y = __ldg(&b3[n0 + j*8 + 2*tig + 1]);
    }
    const uint4* fragp = &g_w3pack[(w * 16) * 32 + lane];

    // ---- Phase A: layers 0-2 for this warp's 4 samples of group gg ----
    auto phaseA = [&](int gg) {
        const int S0 = gg * 32 + w * 4;
        if (lane < 20) {
            int pl = lane >= 10;
            int i  = lane % 10;
            int sb = S0 + pl * 2;
            s_pair[w][pl][i] = make_float2(__ldg(&cond[sb*10 + i]), __ldg(&cond[sb*10 + 10 + i]));
        }
        __syncwarp();

        // layer 0: 10 -> 32 (short; ILP 2)
        {
            ull acc[2];
            ull b = dup2(__ldg(&b0[lane]));
            acc[0] = b; acc[1] = b;
            #pragma unroll
            for (int k = 0; k < 10; k += 2) {
                ull wkA = dup2(__ldg(&w0[k*32 + lane]));
                ull wkB = dup2(__ldg(&w0[(k+1)*32 + lane]));
                #pragma unroll
                for (int p = 0; p < 2; ++p) {
                    ulonglong2 h2 = *(const ulonglong2*)&s_pair[w][p][k];
                    acc[p] = fma2(h2.x, wkA, acc[p]);
                    acc[p] = fma2(h2.y, wkB, acc[p]);
                }
            }
            __syncwarp();
            #pragma unroll
            for (int p = 0; p < 2; ++p) {
                float2 f = unpk(acc[p]);
                s_pair[w][p][lane] = make_float2(fmaxf(f.x, 0.f), fmaxf(f.y, 0.f));
            }
            __syncwarp();
        }

        // layer 1: 32 -> 32 (k-split: 4 independent chains)
        {
            ull aL[2], aH[2];
            ull b = dup2(__ldg(&b1[lane]));
            aL[0] = b; aL[1] = b;
            aH[0] = dup2(0.f); aH[1] = dup2(0.f);
            #pragma unroll 8
            for (int k = 0; k < 16; k += 2) {
                ull wkA = dup2(__ldg(&w1[k*32 + lane]));
                ull wkB = dup2(__ldg(&w1[(k+1)*32 + lane]));
                ull wkC = dup2(__ldg(&w1[(k+16)*32 + lane]));
                ull wkD = dup2(__ldg(&w1[(k+17)*32 + lane]));
                #pragma unroll
                for (int p = 0; p < 2; ++p) {
                    ulonglong2 h2 = *(const ulonglong2*)&s_pair[w][p][k];
                    ulonglong2 g2 = *(const ulonglong2*)&s_pair[w][p][k+16];
                    aL[p] = fma2(h2.x, wkA, aL[p]);
                    aL[p] = fma2(h2.y, wkB, aL[p]);
                    aH[p] = fma2(g2.x, wkC, aH[p]);
                    aH[p] = fma2(g2.y, wkD, aH[p]);
                }
            }
            __syncwarp();
            #pragma unroll
            for (int p = 0; p < 2; ++p) {
                float2 f = unpk(add2(aL[p], aH[p]));
                s_pair[w][p][lane] = make_float2(fmaxf(f.x, 0.f), fmaxf(f.y, 0.f));
            }
            __syncwarp();
        }

        // layer 2: 32 -> 32 (k-split), publish to s_hA [sample][k]
        {
            ull aL[2], aH[2];
            ull b = dup2(__ldg(&b2[lane]));
            aL[0] = b; aL[1] = b;
            aH[0] = dup2(0.f); aH[1] = dup2(0.f);
            #pragma unroll 8
            for (int k = 0; k < 16; k += 2) {
                ull wkA = dup2(__ldg(&w2[k*32 + lane]));
                ull wkB = dup2(__ldg(&w2[(k+1)*32 + lane]));
                ull wkC = dup2(__ldg(&w2[(k+16)*32 + lane]));
                ull wkD = dup2(__ldg(&w2[(k+17)*32 + lane]));
                #pragma unroll
                for (int p = 0; p < 2; ++p) {
                    ulonglong2 h2 = *(const ulonglong2*)&s_pair[w][p][k];
                    ulonglong2 g2 = *(const ulonglong2*)&s_pair[w][p][k+16];
                    aL[p] = fma2(h2.x, wkA, aL[p]);
                    aL[p] = fma2(h2.y, wkB, aL[p]);
                    aH[p] = fma2(g2.x, wkC, aH[p]);
                    aH[p] = fma2(g2.y, wkD, aH[p]);
                }
            }
            __syncwarp();
            #pragma unroll
            for (int p = 0; p < 2; ++p) {
                float2 f = unpk(add2(aL[p], aH[p]));
                s_hA[(w*4 + 2*p    ) * HAS + lane] = fmaxf(f.x, 0.f);
                s_hA[(w*4 + 2*p + 1) * HAS + lane] = fmaxf(f.y, 0.f);
            }
        }
    };

    int g = blockIdx.x;
    if (g < GROUPS) phaseA(g);

    for (; g < GROUPS; g += gridDim.x) {
        const int Sblk = g * 32;
        __syncthreads();   // s_hA(g) ready; prior C done with s_hist/s_rows

        // ============ Phase B: layer 3 via mma tf32, ik outer / im inner ============
        float c[2][4][4];
        #pragma unroll
        for (int im = 0; im < 2; ++im)
            #pragma unroll
            for (int j = 0; j < 4; ++j) {
                c[im][j][0] = biasj[j].x; c[im][j][1] = biasj[j].y;
                c[im][j][2] = biasj[j].x; c[im][j][3] = biasj[j].y;
            }

        #pragma unroll
        for (int ik = 0; ik < 4; ++ik) {
            const int k0 = ik * 8;
            uint ah[2][4], al[2][4];
            #pragma unroll
            for (int im = 0; im < 2; ++im) {
                const int r0 = im * 16 + gid;
                float a0 = s_hA[ r0      * HAS + k0 + tig    ];
                float a1 = s_hA[(r0 + 8) * HAS + k0 + tig    ];
                float a2 = s_hA[ r0      * HAS + k0 + tig + 4];
                float a3 = s_hA[(r0 + 8) * HAS + k0 + tig + 4];
                ah[im][0] = to_tf32(a0); al[im][0] = to_tf32(a0 - __uint_as_float(ah[im][0]));
                ah[im][1] = to_tf32(a1); al[im][1] = to_tf32(a1 - __uint_as_float(ah[im][1]));
                ah[im][2] = to_tf32(a2); al[im][2] = to_tf32(a2 - __uint_as_float(ah[im][2]));
                ah[im][3] = to_tf32(a3); al[im][3] = to_tf32(a3 - __uint_as_float(ah[im][3]));
            }
            #pragma unroll
            for (int j = 0; j < 4; ++j) {
                uint4 f = __ldg(&fragp[(ik*4 + j) * 32]);
                #pragma unroll
                for (int im = 0; im < 2; ++im) {
                    mma_tf32(c[im][j], ah[im], f.x, f.y);
                    mma_tf32(c[im][j], ah[im], f.z, f.w);
                    mma_tf32(c[im][j], al[im], f.x, f.y);
                }
            }
        }

        // epilogue: softplus, hist writes, row sums
        #pragma unroll
        for (int im = 0; im < 2; ++im) {
            const int m0 = im * 16 + gid;
            float rs_lo0 = 0.f, rs_hi0 = 0.f, rs_lo8 = 0.f, rs_hi8 = 0.f;
            #pragma unroll
            for (int j = 0; j < 4; ++j) {
                float2 s01 = softplus2(pack2(c[im][j][0], c[im][j][1]));
                float2 s23 = softplus2(pack2(c[im][j][2], c[im][j][3]));
                const int colb = n0 + j*8 + 2*tig;
                *(float2*)&s_hist[m0    ][colb] = s01;
                *(float2*)&s_hist[m0 + 8][colb] = s23;
                float t0 = s01.x + s01.y;
                float t8 = s23.x + s23.y;
                if (j < 2) { rs_lo0 += t0; rs_lo8 += t8; }
                else       { rs_hi0 += t0; rs_hi8 += t8; }
            }
            rs_lo0 += __shfl_xor_sync(FULLM, rs_lo0, 1);
            rs_hi0 += __shfl_xor_sync(FULLM, rs_hi0, 1);
            rs_lo8 += __shfl_xor_sync(FULLM, rs_lo8, 1);
            rs_hi8 += __shfl_xor_sync(FULLM, rs_hi8, 1);
            rs_lo0 += __shfl_xor_sync(FULLM, rs_lo0, 2);
            rs_hi0 += __shfl_xor_sync(FULLM, rs_hi0, 2);
            rs_lo8 += __shfl_xor_sync(FULLM, rs_lo8, 2);
            rs_hi8 += __shfl_xor_sync(FULLM, rs_hi8, 2);
            if (tig == 0) {
                s_rows[m0    ][2*w    ] = rs_lo0;
                s_rows[m0    ][2*w + 1] = rs_hi0;
                s_rows[m0 + 8][2*w    ] = rs_lo8;
                s_rows[m0 + 8][2*w + 1] = rs_hi8;
            }
        }
        __syncthreads();   // s_hist/s_rows ready; s_hA free for next A

        const int gn = g + gridDim.x;
        if (gn < GROUPS) phaseA(gn);

        // ============ Phase C: inverse-CDF sampling (unnormalized compares) ============
        const int li = lane & 15;
        #pragma unroll
        for (int j = 0; j < 2; ++j) {
            const int sa   = w * 4 + 2 * j;
            const int samp = (lane < 16) ? sa : (sa + 1);
            const int S    = Sblk + samp;

            float rowsum = s_rows[samp][li];
            float tot = rowsum;
            #pragma unroll
            for (int o = 1; o < 16; o <<= 1) tot += __shfl_xor_sync(FULLM, tot, o);

            float cdf = rowsum;
            #pragma unroll
            for (int d = 1; d < 16; d <<= 1) {
                float t = __shfl_up_sync(FULLM, cdf, d, 16);
                if (li >= d) cdf += t;
            }

            float u_x = __ldg(&wi[S*2]);
            float u_y = __ldg(&wi[S*2 + 1]);
            float uy  = u_y * tot;

            unsigned bal = __ballot_sync(FULLM, cdf < uy);
            unsigned mym = (lane < 16) ? (bal & 0xFFFFu) : (bal >> 16);
            int   iy   = min(__popc(mym), 15);
            float cdfp = __shfl_sync(FULLM, cdf, max(iy - 1, 0), 16);
            cdfp = (iy > 0) ? cdfp : 0.f;
            float py   = __shfl_sync(FULLM, rowsum, iy, 16);
            float yv   = ((float)iy + __fdividef(uy - cdfp, fmaxf(py, EPSF))) * 0.0625f;

            float hv   = s_hist[samp][iy*16 + li];
            float cdfx = hv;
            #pragma unroll
            for (int d = 1; d < 16; d <<= 1) {
                float t = __shfl_up_sync(FULLM, cdfx, d, 16);
                if (li >= d) cdfx += t;
            }
            float ux = u_x * py;
            unsigned balx = __ballot_sync(FULLM, cdfx < ux);
            unsigned mymx = (lane < 16) ? (balx & 0xFFFFu) : (balx >> 16);
            int   ix    = min(__popc(mymx), 15);
            float cdfxp = __shfl_sync(FULLM, cdfx, max(ix - 1, 0), 16);
            cdfxp = (ix > 0) ? cdfxp : 0.f;
            float px    = __shfl_sync(FULLM, hv, ix, 16);
            float xv    = ((float)ix + __fdividef(ux - cdfxp, fmaxf(px, EPSF))) * 0.0625f;
            float pout  = __fdividef(px, tot) * 64.f;

            if (li == 0) {
                out[S*2]       = xv * 2.f - 1.f;
                out[S*2 + 1]   = yv * 2.f - 1.f;
                out[2*BN + S]  = pout;
            }
        }
    }
}

extern "C" void kernel_launch(void* const* d_in, const int* in_sizes, int n_in,
                              void* d_out, int out_size) {
    const float* wi   = (const float*)d_in[0];
    const float* cond = (const float*)d_in[1];
    const float* w0   = (const float*)d_in[2];
    const float* b0   = (const float*)d_in[3];
    const float* w1   = (const float*)d_in[4];
    const float* b1   = (const float*)d_in[5];
    const float* w2   = (const float*)d_in[6];
    const float* b2   = (const float*)d_in[7];
    const float* w3   = (const float*)d_in[8];
    const float* b3   = (const float*)d_in[9];
    (void)in_sizes; (void)n_in; (void)out_size;
    prep_kernel<<<16, 256>>>(w3);
    hist2d_kernel<<<2048, 256>>>(wi, cond, w0, b0, w1, b1, w2, b2, b3, (float*)d_out);
}

// round 11
// speedup vs baseline: 1.1549x; 1.0268x over previous
#include <cuda_runtime.h>
#include <cstdint>

#define FULLM 0xffffffffu
typedef unsigned long long ull;
typedef unsigned int uint;

static __device__ __forceinline__ ull fma2(ull a, ull b, ull c){
    ull d; asm("fma.rn.f32x2 %0, %1, %2, %3;" : "=l"(d) : "l"(a), "l"(b), "l"(c)); return d;
}
static __device__ __forceinline__ ull mul2(ull a, ull b){
    ull d; asm("mul.rn.f32x2 %0, %1, %2;" : "=l"(d) : "l"(a), "l"(b)); return d;
}
static __device__ __forceinline__ ull dup2(float x){
    ull d; asm("mov.b64 %0, {%1, %1};" : "=l"(d) : "f"(x)); return d;
}
static __device__ __forceinline__ ull pack2(float a, float b){
    ull d; asm("mov.b64 %0, {%1, %2};" : "=l"(d) : "f"(a), "f"(b)); return d;
}
static __device__ __forceinline__ float2 unpk(ull a){
    float2 f; asm("mov.b64 {%0, %1}, %2;" : "=f"(f.x), "=f"(f.y) : "l"(a)); return f;
}
static __device__ __forceinline__ uint to_tf32(float x){
    uint r; asm("cvt.rna.tf32.f32 %0, %1;" : "=r"(r) : "f"(x)); return r;
}
static __device__ __forceinline__ void mma_tf32(float c[4], const uint a[4], uint b0, uint b1){
    asm("mma.sync.aligned.m16n8k8.row.col.f32.tf32.tf32.f32 "
        "{%0,%1,%2,%3}, {%4,%5,%6,%7}, {%8,%9}, {%0,%1,%2,%3};"
        : "+f"(c[0]), "+f"(c[1]), "+f"(c[2]), "+f"(c[3])
        : "r"(a[0]), "r"(a[1]), "r"(a[2]), "r"(a[3]), "r"(b0), "r"(b1));
}

// packed softplus: 1 MUFU/elem; ln(1+e) via degree-9 poly (|err| <= 1.7e-6)
static __device__ __forceinline__ float2 softplus2(ull x){
    ull ax; asm("and.b64 %0, %1, 0x7FFFFFFF7FFFFFFF;" : "=l"(ax) : "l"(x));
    ull t = mul2(ax, dup2(-1.4426950408889634f));
    float2 tf = unpk(t);
    float e0, e1;
    asm("ex2.approx.f32 %0, %1;" : "=f"(e0) : "f"(tf.x));
    asm("ex2.approx.f32 %0, %1;" : "=f"(e1) : "f"(tf.y));
    ull e2 = pack2(e0, e1);
    ull z  = fma2(e2, dup2(0.6666666666666667f), dup2(-0.3333333333333333f));
    ull Q  = dup2(0.1111111111111111f);
    Q = fma2(Q, z, dup2(-0.125f));
    Q = fma2(Q, z, dup2( 0.14285714285714285f));
    Q = fma2(Q, z, dup2(-0.16666666666666666f));
    Q = fma2(Q, z, dup2( 0.2f));
    Q = fma2(Q, z, dup2(-0.25f));
    Q = fma2(Q, z, dup2( 0.3333333333333333f));
    Q = fma2(Q, z, dup2(-0.5f));
    Q = fma2(Q, z, dup2( 1.0f));
    ull L = fma2(Q, z, dup2(0.4054651081081644f));
    float2 xf = unpk(x), Lf = unpk(L);
    return make_float2(fmaxf(xf.x, 0.f) + Lf.x, fmaxf(xf.y, 0.f) + Lf.y);
}

constexpr int   BN     = 262144;
constexpr int   GROUPS = BN / 32;
constexpr int   HPAD   = 272;
constexpr int   AS     = 36;       // activation buffer stride (banks 4g+t all-distinct)
constexpr float EPSF   = 1e-12f;

// w3 fragments: [w][ik][j][lane] -> uint4 {bhi0,bhi1,blo0,blo1}
__device__ uint4 g_w3pack[8 * 4 * 4 * 32];
// w0/w1/w2 fragments: L0 [nt][ks(2)][lane] @0, L1 [nt][ks(4)][lane] @256, L2 @768
__device__ uint4 g_wfrag[1280];

__global__ void prep_kernel(const float* __restrict__ w3, const float* __restrict__ w0,
                            const float* __restrict__ w1, const float* __restrict__ w2) {
    int idx = blockIdx.x * blockDim.x + threadIdx.x;
    int lane = idx & 31;
    int gid = lane >> 2, tig = lane & 3;
    if (idx < 4096) {
        int j = (idx >> 5) & 3, ik = (idx >> 7) & 3, w = idx >> 9;
        int n0 = w * 32;
        float v0 = w3[(ik*8 + tig    )*256 + n0 + j*8 + gid];
        float v1 = w3[(ik*8 + tig + 4)*256 + n0 + j*8 + gid];
        uint h0 = to_tf32(v0), h1 = to_tf32(v1);
        g_w3pack[idx] = make_uint4(h0, h1, to_tf32(v0 - __uint_as_float(h0)),
                                           to_tf32(v1 - __uint_as_float(h1)));
    } else if (idx < 4096 + 256) {
        int t = idx - 4096;                     // L0: (nt*2 + ks)*32 + lane
        int ks = (t >> 5) & 1, nt = t >> 6;
        int n = nt*8 + gid;
        int ka = ks*8 + tig, kb = ks*8 + tig + 4;
        float v0 = (ka < 10) ? w0[ka*32 + n] : 0.f;
        float v1 = (kb < 10) ? w0[kb*32 + n] : 0.f;
        uint h0 = to_tf32(v0), h1 = to_tf32(v1);
        g_wfrag[t] = make_uint4(h0, h1, to_tf32(v0 - __uint_as_float(h0)),
                                        to_tf32(v1 - __uint_as_float(h1)));
    } else if (idx < 4096 + 256 + 1024) {
        int t = idx - 4096 - 256;               // L1/L2: (nt*4 + ks)*32 + lane
        const float* W = (t < 512) ? w1 : w2;
        int tt = t & 511;
        int ks = (tt >> 5) & 3, nt = tt >> 7;
        int n = nt*8 + gid;
        float v0 = W[(ks*8 + tig    )*32 + n];
        float v1 = W[(ks*8 + tig + 4)*32 + n];
        uint h0 = to_tf32(v0), h1 = to_tf32(v1);
        g_wfrag[256 + t] = make_uint4(h0, h1, to_tf32(v0 - __uint_as_float(h0)),
                                              to_tf32(v1 - __uint_as_float(h1)));
    }
}

__global__ __launch_bounds__(256, 3)
void hist2d_kernel(const float* __restrict__ wi, const float* __restrict__ cond,
                   const float* __restrict__ b0, const float* __restrict__ b1,
                   const float* __restrict__ b2, const float* __restrict__ b3,
                   float* __restrict__ out)
{
    __shared__ __align__(16) float bufA[32 * AS];
    __shared__ __align__(16) float bufB[32 * AS];
    __shared__ float s_rows[32][17];
    __shared__ __align__(16) float s_hist[32][HPAD];

    const int tid  = threadIdx.x;
    const int lane = tid & 31;
    const int w    = tid >> 5;
    const int gid  = lane >> 2;
    const int tig  = lane & 3;
    const int mt   = (w & 1) * 16;     // layer m-tile
    const int nt   = w >> 1;           // layer n-tile (0..3)
    const int n8   = nt * 8;
    const int n0   = w * 32;           // phase-B col base

    const float2 bs0 = make_float2(__ldg(&b0[n8 + 2*tig]), __ldg(&b0[n8 + 2*tig + 1]));
    const float2 bs1 = make_float2(__ldg(&b1[n8 + 2*tig]), __ldg(&b1[n8 + 2*tig + 1]));
    const float2 bs2 = make_float2(__ldg(&b2[n8 + 2*tig]), __ldg(&b2[n8 + 2*tig + 1]));
    float2 biasj[4];
    #pragma unroll
    for (int j = 0; j < 4; ++j) {
        biasj[j].x = __ldg(&b3[n0 + j*8 + 2*tig]);
        biasj[j].y = __ldg(&b3[n0 + j*8 + 2*tig + 1]);
    }
    const uint4* f0 = &g_wfrag[nt*64 + lane];
    const uint4* f1 = &g_wfrag[256 + nt*128 + lane];
    const uint4* f2 = &g_wfrag[768 + nt*128 + lane];
    const uint4* fragp = &g_w3pack[(w * 16) * 32 + lane];

    // one MLP layer (m16n8 tile per warp) via 3xTF32 mma, relu, write to dst
    auto layer = [&](const float* src, float* dst, const uint4* wf, float2 bs, int ksteps) {
        float c[4] = {0.f, 0.f, 0.f, 0.f};
        #pragma unroll 4
        for (int ks = 0; ks < ksteps; ++ks) {
            const int k0 = ks * 8;
            float a0 = src[(mt + gid    ) * AS + k0 + tig    ];
            float a1 = src[(mt + gid + 8) * AS + k0 + tig    ];
            float a2 = src[(mt + gid    ) * AS + k0 + tig + 4];
            float a3 = src[(mt + gid + 8) * AS + k0 + tig + 4];
            uint ah[4], al[4];
            ah[0] = to_tf32(a0); al[0] = to_tf32(a0 - __uint_as_float(ah[0]));
            ah[1] = to_tf32(a1); al[1] = to_tf32(a1 - __uint_as_float(ah[1]));
            ah[2] = to_tf32(a2); al[2] = to_tf32(a2 - __uint_as_float(ah[2]));
            ah[3] = to_tf32(a3); al[3] = to_tf32(a3 - __uint_as_float(ah[3]));
            uint4 f = __ldg(&wf[ks * 32]);
            mma_tf32(c, ah, f.x, f.y);
            mma_tf32(c, ah, f.z, f.w);
            mma_tf32(c, al, f.x, f.y);
        }
        c[0] = fmaxf(c[0] + bs.x, 0.f);
        c[1] = fmaxf(c[1] + bs.y, 0.f);
        c[2] = fmaxf(c[2] + bs.x, 0.f);
        c[3] = fmaxf(c[3] + bs.y, 0.f);
        *(float2*)&dst[(mt + gid    ) * AS + n8 + 2*tig] = make_float2(c[0], c[1]);
        *(float2*)&dst[(mt + gid + 8) * AS + n8 + 2*tig] = make_float2(c[2], c[3]);
    };

    for (int g = blockIdx.x; g < GROUPS; g += gridDim.x) {
        const int Sblk = g * 32;

        // ---- load cond into bufA (strided: 320 > blockDim!) + zero-pad K 10..15 ----
        #pragma unroll
        for (int i = tid; i < 320; i += 256) bufA[(i/10)*AS + (i%10)] = __ldg(&cond[Sblk*10 + i]);
        if (tid < 192) bufA[(tid/6)*AS + 10 + (tid%6)] = 0.f;
        __syncthreads();

        layer(bufA, bufB, f0, bs0, 2);   // 10(16) -> 32
        __syncthreads();
        layer(bufB, bufA, f1, bs1, 4);   // 32 -> 32
        __syncthreads();
        layer(bufA, bufB, f2, bs2, 4);   // 32 -> 32
        __syncthreads();

        // ============ Phase B: layer 3 via mma tf32, ik outer / im inner ============
        float c[2][4][4];
        #pragma unroll
        for (int im = 0; im < 2; ++im)
            #pragma unroll
            for (int j = 0; j < 4; ++j) {
                c[im][j][0] = biasj[j].x; c[im][j][1] = biasj[j].y;
                c[im][j][2] = biasj[j].x; c[im][j][3] = biasj[j].y;
            }

        #pragma unroll
        for (int ik = 0; ik < 4; ++ik) {
            const int k0 = ik * 8;
            uint ah[2][4], al[2][4];
            #pragma unroll
            for (int im = 0; im < 2; ++im) {
                const int r0 = im * 16 + gid;
                float a0 = bufB[ r0      * AS + k0 + tig    ];
                float a1 = bufB[(r0 + 8) * AS + k0 + tig    ];
                float a2 = bufB[ r0      * AS + k0 + tig + 4];
                float a3 = bufB[(r0 + 8) * AS + k0 + tig + 4];
                ah[im][0] = to_tf32(a0); al[im][0] = to_tf32(a0 - __uint_as_float(ah[im][0]));
                ah[im][1] = to_tf32(a1); al[im][1] = to_tf32(a1 - __uint_as_float(ah[im][1]));
                ah[im][2] = to_tf32(a2); al[im][2] = to_tf32(a2 - __uint_as_float(ah[im][2]));
                ah[im][3] = to_tf32(a3); al[im][3] = to_tf32(a3 - __uint_as_float(ah[im][3]));
            }
            #pragma unroll
            for (int j = 0; j < 4; ++j) {
                uint4 f = __ldg(&fragp[(ik*4 + j) * 32]);
                #pragma unroll
                for (int im = 0; im < 2; ++im) {
                    mma_tf32(c[im][j], ah[im], f.x, f.y);
                    mma_tf32(c[im][j], ah[im], f.z, f.w);
                    mma_tf32(c[im][j], al[im], f.x, f.y);
                }
            }
        }

        // epilogue: softplus, hist writes, row sums
        #pragma unroll
        for (int im = 0; im < 2; ++im) {
            const int m0 = im * 16 + gid;
            float rs_lo0 = 0.f, rs_hi0 = 0.f, rs_lo8 = 0.f, rs_hi8 = 0.f;
            #pragma unroll
            for (int j = 0; j < 4; ++j) {
                float2 s01 = softplus2(pack2(c[im][j][0], c[im][j][1]));
                float2 s23 = softplus2(pack2(c[im][j][2], c[im][j][3]));
                const int colb = n0 + j*8 + 2*tig;
                *(float2*)&s_hist[m0    ][colb] = s01;
                *(float2*)&s_hist[m0 + 8][colb] = s23;
                float t0 = s01.x + s01.y;
                float t8 = s23.x + s23.y;
                if (j < 2) { rs_lo0 += t0; rs_lo8 += t8; }
                else       { rs_hi0 += t0; rs_hi8 += t8; }
            }
            rs_lo0 += __shfl_xor_sync(FULLM, rs_lo0, 1);
            rs_hi0 += __shfl_xor_sync(FULLM, rs_hi0, 1);
            rs_lo8 += __shfl_xor_sync(FULLM, rs_lo8, 1);
            rs_hi8 += __shfl_xor_sync(FULLM, rs_hi8, 1);
            rs_lo0 += __shfl_xor_sync(FULLM, rs_lo0, 2);
            rs_hi0 += __shfl_xor_sync(FULLM, rs_hi0, 2);
            rs_lo8 += __shfl_xor_sync(FULLM, rs_lo8, 2);
            rs_hi8 += __shfl_xor_sync(FULLM, rs_hi8, 2);
            if (tig == 0) {
                s_rows[m0    ][2*w    ] = rs_lo0;
                s_rows[m0    ][2*w + 1] = rs_hi0;
                s_rows[m0 + 8][2*w    ] = rs_lo8;
                s_rows[m0 + 8][2*w + 1] = rs_hi8;
            }
        }
        __syncthreads();

        // ============ Phase C: inverse-CDF sampling (unnormalized compares) ============
        const int li = lane & 15;
        #pragma unroll
        for (int j = 0; j < 2; ++j) {
            const int sa   = w * 4 + 2 * j;
            const int samp = (lane < 16) ? sa : (sa + 1);
            const int S    = Sblk + samp;

            float rowsum = s_rows[samp][li];
            float tot = rowsum;
            #pragma unroll
            for (int o = 1; o < 16; o <<= 1) tot += __shfl_xor_sync(FULLM, tot, o);

            float cdf = rowsum;
            #pragma unroll
            for (int d = 1; d < 16; d <<= 1) {
                float t = __shfl_up_sync(FULLM, cdf, d, 16);
                if (li >= d) cdf += t;
            }

            float u_x = __ldg(&wi[S*2]);
            float u_y = __ldg(&wi[S*2 + 1]);
            float uy  = u_y * tot;

            unsigned bal = __ballot_sync(FULLM, cdf < uy);
            unsigned mym = (lane < 16) ? (bal & 0xFFFFu) : (bal >> 16);
            int   iy   = min(__popc(mym), 15);
            float cdfp = __shfl_sync(FULLM, cdf, max(iy - 1, 0), 16);
            cdfp = (iy > 0) ? cdfp : 0.f;
            float py   = __shfl_sync(FULLM, rowsum, iy, 16);
            float yv   = ((float)iy + __fdividef(uy - cdfp, fmaxf(py, EPSF))) * 0.0625f;

            float hv   = s_hist[samp][iy*16 + li];
            float cdfx = hv;
            #pragma unroll
            for (int d = 1; d < 16; d <<= 1) {
                float t = __shfl_up_sync(FULLM, cdfx, d, 16);
                if (li >= d) cdfx += t;
            }
            float ux = u_x * py;
            unsigned balx = __ballot_sync(FULLM, cdfx < ux);
            unsigned mymx = (lane < 16) ? (balx & 0xFFFFu) : (balx >> 16);
            int   ix    = min(__popc(mymx), 15);
            float cdfxp = __shfl_sync(FULLM, cdfx, max(ix - 1, 0), 16);
            cdfxp = (ix > 0) ? cdfxp : 0.f;
            float px    = __shfl_sync(FULLM, hv, ix, 16);
            float xv    = ((float)ix + __fdividef(ux - cdfxp, fmaxf(px, EPSF))) * 0.0625f;
            float pout  = __fdividef(px, tot) * 64.f;

            if (li == 0) {
                out[S*2]       = xv * 2.f - 1.f;
                out[S*2 + 1]   = yv * 2.f - 1.f;
                out[2*BN + S]  = pout;
            }
        }
        __syncthreads();   // s_hist free before next group's phase-B epilogue
    }
}

extern "C" void kernel_launch(void* const* d_in, const int* in_sizes, int n_in,
                              void* d_out, int out_size) {
    const float* wi   = (const float*)d_in[0];
    const float* cond = (const float*)d_in[1];
    const float* w0   = (const float*)d_in[2];
    const float* b0   = (const float*)d_in[3];
    const float* w1   = (const float*)d_in[4];
    const float* b1   = (const float*)d_in[5];
    const float* w2   = (const float*)d_in[6];
    const float* b2   = (const float*)d_in[7];
    const float* w3   = (const float*)d_in[8];
    const float* b3   = (const float*)d_in[9];
    (void)in_sizes; (void)n_in; (void)out_size;
    prep_kernel<<<21, 256>>>(w3, w0, w1, w2);
    hist2d_kernel<<<2048, 256>>>(wi, cond, b0, b1, b2, b3, (float*)d_out);
}